// round 13
// baseline (speedup 1.0000x reference)
#include <cuda_runtime.h>
#include <float.h>

#define NB    4
#define NP    64
#define BP    256           // NB*NP query rows
#define D     768
#define NN    2048
#define RR    12
#define TOPK  16
#define KSPLIT 32           // split-K for out GEMM
#define DSPLIT 8            // split-D for scores GEMM
#define ADJ_BLOCKS 1184

// ---- scratch (static __device__, no allocations) ----
__device__ float g_rnorm[NN];              // 1/||keys_param row||
__device__ float g_spart[DSPLIT][BP * NN]; // scores partials     16.8 MB
__device__ float g_adjsum[NN * NN];        // sum_r adjacency     16.8 MB
__device__ float g_nei[BP * NN];           //                      2.0 MB
__device__ float g_part[KSPLIT][BP * D];   // split-K partials    25.2 MB

#define FMA_F32X2(d, a, b, c) \
    asm("fma.rn.f32x2 %0, %1, %2, %3;" : "=l"(d) : "l"(a), "l"(b), "l"(c))

// ---------------------------------------------------------------------------
// K1: fused adj_sum (sum_r adjacency, 201 MB stream) + key inverse norms.
// ---------------------------------------------------------------------------
__global__ void k_adjsum_rnorm(const float* __restrict__ adj,
                               const float* __restrict__ kp) {
    if (blockIdx.x >= ADJ_BLOCKS) {
        int bb = blockIdx.x - ADJ_BLOCKS;
        int w = threadIdx.x >> 5, lane = threadIdx.x & 31;
        for (int rr = 0; rr < 16; rr++) {
            int row = bb * 128 + rr * 8 + w;
            const float* src = kp + (long long)row * D;
            float ss = 0.f;
            #pragma unroll
            for (int i = 0; i < D / 32; i++) { float v = src[i * 32 + lane]; ss += v * v; }
            #pragma unroll
            for (int o = 16; o; o >>= 1) ss += __shfl_xor_sync(0xffffffff, ss, o);
            if (lane == 0) g_rnorm[row] = rsqrtf(ss + 1e-12f);
        }
        return;
    }
    const long long t4 = (long long)NN * NN / 4;
    const long long S = (long long)ADJ_BLOCKS * 256;
    const float4* a = (const float4*)adj;
    float4* o = (float4*)g_adjsum;
    for (long long i = (long long)blockIdx.x * 256 + threadIdx.x; i < t4; i += 2 * S) {
        long long j = i + S;
        bool h2 = j < t4;
        float4 acc0 = __ldcs(&a[i]);
        float4 acc1 = h2 ? __ldcs(&a[j]) : make_float4(0.f, 0.f, 0.f, 0.f);
        #pragma unroll
        for (int r = 1; r < RR; r++) {
            float4 v0 = __ldcs(&a[i + (long long)r * t4]);
            float4 v1 = h2 ? __ldcs(&a[j + (long long)r * t4]) : make_float4(0.f, 0.f, 0.f, 0.f);
            acc0.x += v0.x; acc0.y += v0.y; acc0.z += v0.z; acc0.w += v0.w;
            acc1.x += v1.x; acc1.y += v1.y; acc1.z += v1.z; acc1.w += v1.w;
        }
        o[i] = acc0;
        if (h2) o[j] = acc1;
    }
}

// ---------------------------------------------------------------------------
// K2: spart[z][m,n] = sum_{d in z-chunk} pos[m,d]*kp[n,d]*rnorm[n]  (NT)
// 128x128 block tile, BK=16, 256 thr, 8x8 thread tile, f32x2, prefetch
// ---------------------------------------------------------------------------
__global__ __launch_bounds__(256, 2)
void k_scores(const float* __restrict__ pos, const float* __restrict__ kp) {
    __shared__ float Asd[16][260];   // dup pairs: Asd[k][2m]=Asd[k][2m+1]=A[m][k]
    __shared__ float Bs[16][132];
    int n0 = blockIdx.x * 128, m0 = blockIdx.y * 128;
    int z = blockIdx.z;
    int t = threadIdx.x;
    int tx = t & 15, ty = t >> 4;        // tx: n-oct, ty: m-oct
    int am = t >> 1, aq = t & 1;         // loader: row am, k-quads {aq, aq+2}
    const int KCH = D / DSPLIT, NIT = KCH / 16;
    int kb = z * KCH;
    float brn = g_rnorm[n0 + am];

    float4 avP[2], bvP[2];
    #pragma unroll
    for (int h = 0; h < 2; h++) {
        int q = aq + 2 * h;
        avP[h] = *(const float4*)&pos[(long long)(m0 + am) * D + kb + q * 4];
        bvP[h] = *(const float4*)&kp[(long long)(n0 + am) * D + kb + q * 4];
    }
    unsigned long long acc[8][4] = {};
    for (int it = 0; it < NIT; it++) {
        __syncthreads();
        #pragma unroll
        for (int h = 0; h < 2; h++) {
            int q = aq + 2 * h;
            float4 av = avP[h];
            *(float2*)&Asd[q * 4 + 0][2 * am] = make_float2(av.x, av.x);
            *(float2*)&Asd[q * 4 + 1][2 * am] = make_float2(av.y, av.y);
            *(float2*)&Asd[q * 4 + 2][2 * am] = make_float2(av.z, av.z);
            *(float2*)&Asd[q * 4 + 3][2 * am] = make_float2(av.w, av.w);
            float4 bv = bvP[h];
            Bs[q * 4 + 0][am] = bv.x * brn;
            Bs[q * 4 + 1][am] = bv.y * brn;
            Bs[q * 4 + 2][am] = bv.z * brn;
            Bs[q * 4 + 3][am] = bv.w * brn;
        }
        __syncthreads();
        if (it + 1 < NIT) {
            int k0 = kb + (it + 1) * 16;
            #pragma unroll
            for (int h = 0; h < 2; h++) {
                int q = aq + 2 * h;
                avP[h] = *(const float4*)&pos[(long long)(m0 + am) * D + k0 + q * 4];
                bvP[h] = *(const float4*)&kp[(long long)(n0 + am) * D + k0 + q * 4];
            }
        }
        #pragma unroll
        for (int kk = 0; kk < 16; kk++) {
            ulonglong2 a01 = *(const ulonglong2*)&Asd[kk][ty * 16];
            ulonglong2 a23 = *(const ulonglong2*)&Asd[kk][ty * 16 + 4];
            ulonglong2 a45 = *(const ulonglong2*)&Asd[kk][ty * 16 + 8];
            ulonglong2 a67 = *(const ulonglong2*)&Asd[kk][ty * 16 + 12];
            ulonglong2 b01 = *(const ulonglong2*)&Bs[kk][tx * 8];
            ulonglong2 b23 = *(const ulonglong2*)&Bs[kk][tx * 8 + 4];
            unsigned long long Ar[8] = {a01.x, a01.y, a23.x, a23.y,
                                        a45.x, a45.y, a67.x, a67.y};
            unsigned long long Br[4] = {b01.x, b01.y, b23.x, b23.y};
            #pragma unroll
            for (int mm = 0; mm < 8; mm++)
                #pragma unroll
                for (int np = 0; np < 4; np++)
                    FMA_F32X2(acc[mm][np], Ar[mm], Br[np], acc[mm][np]);
        }
    }
    #pragma unroll
    for (int mm = 0; mm < 8; mm++) {
        float2 c0 = *(float2*)&acc[mm][0], c1 = *(float2*)&acc[mm][1];
        float2 c2 = *(float2*)&acc[mm][2], c3 = *(float2*)&acc[mm][3];
        long long base = (long long)(m0 + ty * 8 + mm) * NN + n0 + tx * 8;
        *(float4*)&g_spart[z][base]     = make_float4(c0.x, c0.y, c1.x, c1.y);
        *(float4*)&g_spart[z][base + 4] = make_float4(c2.x, c2.y, c3.x, c3.y);
    }
}

// ---------------------------------------------------------------------------
// K3: fused (scores partial sum) + top-16 + softmax + nei gather.
// Block per row, 512 threads.
// ---------------------------------------------------------------------------
__global__ void k_topknei() {
    int row = blockIdx.x;
    int w = threadIdx.x >> 5, lane = threadIdx.x & 31;
    int tid = threadIdx.x;
    __shared__ float cv[8][TOPK];
    __shared__ int   ci[8][TOPK];
    __shared__ float swgt[TOPK];
    __shared__ int   sid[TOPK];
    __shared__ float rv_[TOPK];

    if (w < 8) {
        float4 x = {0.f, 0.f, 0.f, 0.f}, y = {0.f, 0.f, 0.f, 0.f};
        #pragma unroll
        for (int z = 0; z < DSPLIT; z++) {
            const float4* p = (const float4*)(g_spart[z] + (long long)row * NN);
            float4 xa = p[w * 64 + lane];
            float4 ya = p[w * 64 + 32 + lane];
            x.x += xa.x; x.y += xa.y; x.z += xa.z; x.w += xa.w;
            y.x += ya.x; y.y += ya.y; y.z += ya.z; y.w += ya.w;
        }
        int b0 = (w * 64 + lane) * 4, b1 = (w * 64 + 32 + lane) * 4;
        float v[8]  = {x.x, x.y, x.z, x.w, y.x, y.y, y.z, y.w};
        int   id[8] = {b0, b0 + 1, b0 + 2, b0 + 3, b1, b1 + 1, b1 + 2, b1 + 3};

        // descending sort, tie -> smaller index (19-CE Batcher network)
        #define CE(i, j) do {                                                 \
            float _av = v[i], _bv = v[j]; int _ai = id[i], _bi = id[j];       \
            bool _sw = (_bv > _av) || (_bv == _av && _bi < _ai);              \
            v[i]  = _sw ? _bv : _av;  id[i] = _sw ? _bi : _ai;                \
            v[j]  = _sw ? _av : _bv;  id[j] = _sw ? _ai : _bi;                \
        } while (0)
        CE(0,1); CE(2,3); CE(4,5); CE(6,7);
        CE(0,2); CE(1,3); CE(4,6); CE(5,7);
        CE(1,2); CE(5,6);
        CE(0,4); CE(1,5); CE(2,6); CE(3,7);
        CE(2,4); CE(3,5);
        CE(1,2); CE(3,4); CE(5,6);
        #undef CE

        #pragma unroll 1
        for (int r = 0; r < TOPK; r++) {
            float wv = v[0]; int wi = id[0];
            #pragma unroll
            for (int o = 16; o; o >>= 1) {
                float ov = __shfl_xor_sync(0xffffffff, wv, o);
                int   oi = __shfl_xor_sync(0xffffffff, wi, o);
                if (ov > wv || (ov == wv && oi < wi)) { wv = ov; wi = oi; }
            }
            if (wi == id[0]) {
                #pragma unroll
                for (int q = 0; q < 7; q++) { v[q] = v[q + 1]; id[q] = id[q + 1]; }
                v[7] = -FLT_MAX; id[7] = 1 << 30;
            }
            if (lane == 0) { cv[w][r] = wv; ci[w][r] = wi; }
        }
    }
    __syncthreads();

    if (w == 0) {
        int p = 0;
        #pragma unroll 1
        for (int r = 0; r < TOPK; r++) {
            float hv = (lane < 8) ? cv[lane][p] : -FLT_MAX;
            int   hi = (lane < 8) ? ci[lane][p] : (1 << 30);
            float wv = hv; int wi = hi;
            #pragma unroll
            for (int o = 16; o; o >>= 1) {
                float ov = __shfl_xor_sync(0xffffffff, wv, o);
                int   oi = __shfl_xor_sync(0xffffffff, wi, o);
                if (ov > wv || (ov == wv && oi < wi)) { wv = ov; wi = oi; }
            }
            if (lane < 8 && wi == hi) p++;
            if (lane == 0) { rv_[r] = wv; sid[r] = wi; }
        }
        __syncwarp();
        if (lane < TOPK) {
            float e = expf(rv_[lane] - rv_[0]);
            float sum = e;
            #pragma unroll
            for (int o = 1; o < TOPK; o <<= 1)
                sum += __shfl_xor_sync(0xffff, sum, o);
            swgt[lane] = e / sum;
        }
    }
    __syncthreads();

    float wgt[TOPK]; int idn[TOPK];
    #pragma unroll
    for (int k = 0; k < TOPK; k++) { wgt[k] = swgt[k]; idn[k] = sid[k]; }
    const float4* a4 = (const float4*)g_adjsum;
    float4 acc = {0.f, 0.f, 0.f, 0.f};
    #pragma unroll
    for (int k = 0; k < TOPK; k++) {
        float4 vv = a4[(long long)idn[k] * (NN / 4) + tid];
        float wk = wgt[k];
        acc.x += wk * vv.x; acc.y += wk * vv.y; acc.z += wk * vv.z; acc.w += wk * vv.w;
    }
    ((float4*)g_nei)[(long long)row * (NN / 4) + tid] = acc;
}

// ---------------------------------------------------------------------------
// K4: partial[z][m,d] = sum_{n in z-chunk} nei[m,n]*kp[n,d]*rnorm[n]
// 128x128 block tile, BK=16, 256 thr, 8x8 thread tile, f32x2, prefetch
// ---------------------------------------------------------------------------
__global__ __launch_bounds__(256, 2)
void k_out_part(const float* __restrict__ kp) {
    __shared__ float Asd[16][260];
    __shared__ float Bs[16][132];
    int d0 = blockIdx.x * 128, m0 = blockIdx.y * 128;
    int kz = blockIdx.z;
    int t = threadIdx.x;
    int tx = t & 15, ty = t >> 4;
    int am = t >> 1, aq = t & 1;         // A loader: row am, k-quads {aq, aq+2}
    int bk = t >> 4, bq = t & 15;        // B loader: k-row bk, n-quads {bq, bq+16}
    const int KCH = NN / KSPLIT, NIT = KCH / 16;
    int kb = kz * KCH;

    float4 avP[2], bvP[2]; float brnP;
    brnP = g_rnorm[kb + bk];
    #pragma unroll
    for (int h = 0; h < 2; h++) {
        int q = aq + 2 * h;
        avP[h] = *(const float4*)&g_nei[(long long)(m0 + am) * NN + kb + q * 4];
        bvP[h] = *(const float4*)&kp[(long long)(kb + bk) * D + d0 + (bq + 16 * h) * 4];
    }
    unsigned long long acc[8][4] = {};
    for (int it = 0; it < NIT; it++) {
        __syncthreads();
        #pragma unroll
        for (int h = 0; h < 2; h++) {
            int q = aq + 2 * h;
            float4 av = avP[h];
            *(float2*)&Asd[q * 4 + 0][2 * am] = make_float2(av.x, av.x);
            *(float2*)&Asd[q * 4 + 1][2 * am] = make_float2(av.y, av.y);
            *(float2*)&Asd[q * 4 + 2][2 * am] = make_float2(av.z, av.z);
            *(float2*)&Asd[q * 4 + 3][2 * am] = make_float2(av.w, av.w);
            float4 bv = bvP[h];
            bv.x *= brnP; bv.y *= brnP; bv.z *= brnP; bv.w *= brnP;
            *(float4*)&Bs[bk][(bq + 16 * h) * 4] = bv;
        }
        __syncthreads();
        if (it + 1 < NIT) {
            int k0 = kb + (it + 1) * 16;
            brnP = g_rnorm[k0 + bk];
            #pragma unroll
            for (int h = 0; h < 2; h++) {
                int q = aq + 2 * h;
                avP[h] = *(const float4*)&g_nei[(long long)(m0 + am) * NN + k0 + q * 4];
                bvP[h] = *(const float4*)&kp[(long long)(k0 + bk) * D + d0 + (bq + 16 * h) * 4];
            }
        }
        #pragma unroll
        for (int kk = 0; kk < 16; kk++) {
            ulonglong2 a01 = *(const ulonglong2*)&Asd[kk][ty * 16];
            ulonglong2 a23 = *(const ulonglong2*)&Asd[kk][ty * 16 + 4];
            ulonglong2 a45 = *(const ulonglong2*)&Asd[kk][ty * 16 + 8];
            ulonglong2 a67 = *(const ulonglong2*)&Asd[kk][ty * 16 + 12];
            ulonglong2 b01 = *(const ulonglong2*)&Bs[kk][tx * 8];
            ulonglong2 b23 = *(const ulonglong2*)&Bs[kk][tx * 8 + 4];
            unsigned long long Ar[8] = {a01.x, a01.y, a23.x, a23.y,
                                        a45.x, a45.y, a67.x, a67.y};
            unsigned long long Br[4] = {b01.x, b01.y, b23.x, b23.y};
            #pragma unroll
            for (int mm = 0; mm < 8; mm++)
                #pragma unroll
                for (int np = 0; np < 4; np++)
                    FMA_F32X2(acc[mm][np], Ar[mm], Br[np], acc[mm][np]);
        }
    }
    #pragma unroll
    for (int mm = 0; mm < 8; mm++) {
        float2 c0 = *(float2*)&acc[mm][0], c1 = *(float2*)&acc[mm][1];
        float2 c2 = *(float2*)&acc[mm][2], c3 = *(float2*)&acc[mm][3];
        long long base = (long long)(m0 + ty * 8 + mm) * D + d0 + tx * 8;
        *(float4*)&g_part[kz][base]     = make_float4(c0.x, c0.y, c1.x, c1.y);
        *(float4*)&g_part[kz][base + 4] = make_float4(c2.x, c2.y, c3.x, c3.y);
    }
}

// K5: out = sum_z partial[z]
__global__ void k_reduce(float* __restrict__ out) {
    int i = blockIdx.x * blockDim.x + threadIdx.x;     // 49152 float4
    float4 acc = {0.f, 0.f, 0.f, 0.f};
    #pragma unroll
    for (int z = 0; z < KSPLIT; z++) {
        float4 v = ((const float4*)g_part[z])[i];
        acc.x += v.x; acc.y += v.y; acc.z += v.z; acc.w += v.w;
    }
    ((float4*)out)[i] = acc;
}

// ---------------------------------------------------------------------------
extern "C" void kernel_launch(void* const* d_in, const int* in_sizes, int n_in,
                              void* d_out, int out_size) {
    const float* pos = (const float*)d_in[0];   // (4,64,768) f32
    const float* kp  = (const float*)d_in[1];   // (2048,768) f32
    const float* adj = (const float*)d_in[2];   // (12,2048,2048) f32
    float* out = (float*)d_out;                 // (4,64,768) f32

    k_adjsum_rnorm<<<ADJ_BLOCKS + 16, 256>>>(adj, kp);
    k_scores<<<dim3(NN / 128, BP / 128, DSPLIT), 256>>>(pos, kp);
    k_topknei<<<BP, 512>>>();
    k_out_part<<<dim3(D / 128, BP / 128, KSPLIT), 256>>>(kp);
    k_reduce<<<BP * D / 4 / 256, 256>>>(out);
}

// round 14
// speedup vs baseline: 1.2107x; 1.2107x over previous
#include <cuda_runtime.h>
#include <float.h>

#define NB    4
#define NP    64
#define BP    256           // NB*NP query rows
#define D     768
#define NN    2048
#define RR    12
#define TOPK  16
#define KSPLIT 8            // split-K for out GEMM
#define DSPLIT 4            // split-D for scores GEMM
#define ADJ_BLOCKS 1184

// ---- scratch (static __device__, no allocations) ----
__device__ float g_rnorm[NN];              // 1/||keys_param row||
__device__ float g_spart[DSPLIT][BP * NN]; // scores partials      8.4 MB
__device__ float g_adjsum[NN * NN];        // sum_r adjacency     16.8 MB
__device__ float g_nei[BP * NN];           //                      2.0 MB
__device__ float g_part[KSPLIT][BP * D];   // split-K partials     6.3 MB

#define FMA_F32X2(d, a, b, c) \
    asm("fma.rn.f32x2 %0, %1, %2, %3;" : "=l"(d) : "l"(a), "l"(b), "l"(c))
#define PACK_DUP(d, a) \
    asm("mov.b64 %0, {%1, %1};" : "=l"(d) : "f"(a))

// ---------------------------------------------------------------------------
// K1: fused adj_sum (sum_r adjacency, 201 MB stream) + key inverse norms.
// ---------------------------------------------------------------------------
__global__ void k_adjsum_rnorm(const float* __restrict__ adj,
                               const float* __restrict__ kp) {
    if (blockIdx.x >= ADJ_BLOCKS) {
        int bb = blockIdx.x - ADJ_BLOCKS;
        int w = threadIdx.x >> 5, lane = threadIdx.x & 31;
        for (int rr = 0; rr < 16; rr++) {
            int row = bb * 128 + rr * 8 + w;
            const float* src = kp + (long long)row * D;
            float ss = 0.f;
            #pragma unroll
            for (int i = 0; i < D / 32; i++) { float v = src[i * 32 + lane]; ss += v * v; }
            #pragma unroll
            for (int o = 16; o; o >>= 1) ss += __shfl_xor_sync(0xffffffff, ss, o);
            if (lane == 0) g_rnorm[row] = rsqrtf(ss + 1e-12f);
        }
        return;
    }
    const long long t4 = (long long)NN * NN / 4;
    const long long S = (long long)ADJ_BLOCKS * 256;
    const float4* a = (const float4*)adj;
    float4* o = (float4*)g_adjsum;
    for (long long i = (long long)blockIdx.x * 256 + threadIdx.x; i < t4; i += 2 * S) {
        long long j = i + S;
        bool h2 = j < t4;
        float4 acc0 = __ldcs(&a[i]);
        float4 acc1 = h2 ? __ldcs(&a[j]) : make_float4(0.f, 0.f, 0.f, 0.f);
        #pragma unroll
        for (int r = 1; r < RR; r++) {
            float4 v0 = __ldcs(&a[i + (long long)r * t4]);
            float4 v1 = h2 ? __ldcs(&a[j + (long long)r * t4]) : make_float4(0.f, 0.f, 0.f, 0.f);
            acc0.x += v0.x; acc0.y += v0.y; acc0.z += v0.z; acc0.w += v0.w;
            acc1.x += v1.x; acc1.y += v1.y; acc1.z += v1.z; acc1.w += v1.w;
        }
        o[i] = acc0;
        if (h2) o[j] = acc1;
    }
}

// ---------------------------------------------------------------------------
// K2: spart[z][m,n] = sum_{d in z-chunk} pos[m,d]*kp[n,d]*rnorm[n]  (NT)
// 64x64 tile, BK=32, 256 thr, 4x4 thread tile, f32x2 with register dup-pack,
// double-buffered smem (1 barrier/tile), LDG reg prefetch.
// ---------------------------------------------------------------------------
__global__ __launch_bounds__(256, 3)
void k_scores(const float* __restrict__ pos, const float* __restrict__ kp) {
    __shared__ float As[2][32][68];
    __shared__ float Bs[2][32][68];
    int n0 = blockIdx.x * 64, m0 = blockIdx.y * 64;
    int z = blockIdx.z;
    int t = threadIdx.x;
    int tx = t & 15, ty = t >> 4;        // tx: n-quad, ty: m-quad
    int am = t >> 2, aq = t & 3;         // loader: row am, k-quads {aq, aq+4}
    const int KCH = D / DSPLIT, NIT = KCH / 32;
    int kb = z * KCH;
    float brn = g_rnorm[n0 + am];

    float4 aP[2], bP[2];
    #pragma unroll
    for (int h = 0; h < 2; h++) {
        int q = aq + 4 * h;
        aP[h] = *(const float4*)&pos[(long long)(m0 + am) * D + kb + q * 4];
        bP[h] = *(const float4*)&kp[(long long)(n0 + am) * D + kb + q * 4];
    }
    #pragma unroll
    for (int h = 0; h < 2; h++) {
        int q = aq + 4 * h;
        As[0][q * 4 + 0][am] = aP[h].x;
        As[0][q * 4 + 1][am] = aP[h].y;
        As[0][q * 4 + 2][am] = aP[h].z;
        As[0][q * 4 + 3][am] = aP[h].w;
        Bs[0][q * 4 + 0][am] = bP[h].x * brn;
        Bs[0][q * 4 + 1][am] = bP[h].y * brn;
        Bs[0][q * 4 + 2][am] = bP[h].z * brn;
        Bs[0][q * 4 + 3][am] = bP[h].w * brn;
    }
    __syncthreads();

    unsigned long long acc[4][2] = {};
    int p = 0;
    for (int it = 0; it < NIT; it++) {
        if (it + 1 < NIT) {
            int k0 = kb + (it + 1) * 32;
            #pragma unroll
            for (int h = 0; h < 2; h++) {
                int q = aq + 4 * h;
                aP[h] = *(const float4*)&pos[(long long)(m0 + am) * D + k0 + q * 4];
                bP[h] = *(const float4*)&kp[(long long)(n0 + am) * D + k0 + q * 4];
            }
        }
        #pragma unroll
        for (int kk = 0; kk < 32; kk++) {
            float4 af = *(const float4*)&As[p][kk][ty * 4];
            ulonglong2 bb = *(const ulonglong2*)&Bs[p][kk][tx * 4];
            unsigned long long a0, a1, a2, a3;
            PACK_DUP(a0, af.x); PACK_DUP(a1, af.y);
            PACK_DUP(a2, af.z); PACK_DUP(a3, af.w);
            FMA_F32X2(acc[0][0], a0, bb.x, acc[0][0]);
            FMA_F32X2(acc[0][1], a0, bb.y, acc[0][1]);
            FMA_F32X2(acc[1][0], a1, bb.x, acc[1][0]);
            FMA_F32X2(acc[1][1], a1, bb.y, acc[1][1]);
            FMA_F32X2(acc[2][0], a2, bb.x, acc[2][0]);
            FMA_F32X2(acc[2][1], a2, bb.y, acc[2][1]);
            FMA_F32X2(acc[3][0], a3, bb.x, acc[3][0]);
            FMA_F32X2(acc[3][1], a3, bb.y, acc[3][1]);
        }
        if (it + 1 < NIT) {
            int pn = p ^ 1;
            #pragma unroll
            for (int h = 0; h < 2; h++) {
                int q = aq + 4 * h;
                As[pn][q * 4 + 0][am] = aP[h].x;
                As[pn][q * 4 + 1][am] = aP[h].y;
                As[pn][q * 4 + 2][am] = aP[h].z;
                As[pn][q * 4 + 3][am] = aP[h].w;
                Bs[pn][q * 4 + 0][am] = bP[h].x * brn;
                Bs[pn][q * 4 + 1][am] = bP[h].y * brn;
                Bs[pn][q * 4 + 2][am] = bP[h].z * brn;
                Bs[pn][q * 4 + 3][am] = bP[h].w * brn;
            }
        }
        __syncthreads();
        p ^= 1;
    }
    #pragma unroll
    for (int mm = 0; mm < 4; mm++) {
        float2 lo = *(float2*)&acc[mm][0];
        float2 hi = *(float2*)&acc[mm][1];
        float4 o = {lo.x, lo.y, hi.x, hi.y};
        *(float4*)&g_spart[z][(long long)(m0 + ty * 4 + mm) * NN + n0 + tx * 4] = o;
    }
}

// ---------------------------------------------------------------------------
// K3: fused (scores partial sum) + top-16 + softmax + nei gather.
// Block per row, 512 threads.
// ---------------------------------------------------------------------------
__global__ void k_topknei() {
    int row = blockIdx.x;
    int w = threadIdx.x >> 5, lane = threadIdx.x & 31;
    int tid = threadIdx.x;
    __shared__ float cv[8][TOPK];
    __shared__ int   ci[8][TOPK];
    __shared__ float swgt[TOPK];
    __shared__ int   sid[TOPK];
    __shared__ float rv_[TOPK];

    if (w < 8) {
        float4 x = {0.f, 0.f, 0.f, 0.f}, y = {0.f, 0.f, 0.f, 0.f};
        #pragma unroll
        for (int z = 0; z < DSPLIT; z++) {
            const float4* p = (const float4*)(g_spart[z] + (long long)row * NN);
            float4 xa = p[w * 64 + lane];
            float4 ya = p[w * 64 + 32 + lane];
            x.x += xa.x; x.y += xa.y; x.z += xa.z; x.w += xa.w;
            y.x += ya.x; y.y += ya.y; y.z += ya.z; y.w += ya.w;
        }
        int b0 = (w * 64 + lane) * 4, b1 = (w * 64 + 32 + lane) * 4;
        float v[8]  = {x.x, x.y, x.z, x.w, y.x, y.y, y.z, y.w};
        int   id[8] = {b0, b0 + 1, b0 + 2, b0 + 3, b1, b1 + 1, b1 + 2, b1 + 3};

        // descending sort, tie -> smaller index (19-CE Batcher network)
        #define CE(i, j) do {                                                 \
            float _av = v[i], _bv = v[j]; int _ai = id[i], _bi = id[j];       \
            bool _sw = (_bv > _av) || (_bv == _av && _bi < _ai);              \
            v[i]  = _sw ? _bv : _av;  id[i] = _sw ? _bi : _ai;                \
            v[j]  = _sw ? _av : _bv;  id[j] = _sw ? _ai : _bi;                \
        } while (0)
        CE(0,1); CE(2,3); CE(4,5); CE(6,7);
        CE(0,2); CE(1,3); CE(4,6); CE(5,7);
        CE(1,2); CE(5,6);
        CE(0,4); CE(1,5); CE(2,6); CE(3,7);
        CE(2,4); CE(3,5);
        CE(1,2); CE(3,4); CE(5,6);
        #undef CE

        #pragma unroll 1
        for (int r = 0; r < TOPK; r++) {
            float wv = v[0]; int wi = id[0];
            #pragma unroll
            for (int o = 16; o; o >>= 1) {
                float ov = __shfl_xor_sync(0xffffffff, wv, o);
                int   oi = __shfl_xor_sync(0xffffffff, wi, o);
                if (ov > wv || (ov == wv && oi < wi)) { wv = ov; wi = oi; }
            }
            if (wi == id[0]) {
                #pragma unroll
                for (int q = 0; q < 7; q++) { v[q] = v[q + 1]; id[q] = id[q + 1]; }
                v[7] = -FLT_MAX; id[7] = 1 << 30;
            }
            if (lane == 0) { cv[w][r] = wv; ci[w][r] = wi; }
        }
    }
    __syncthreads();

    if (w == 0) {
        int p = 0;
        #pragma unroll 1
        for (int r = 0; r < TOPK; r++) {
            float hv = (lane < 8) ? cv[lane][p] : -FLT_MAX;
            int   hi = (lane < 8) ? ci[lane][p] : (1 << 30);
            float wv = hv; int wi = hi;
            #pragma unroll
            for (int o = 16; o; o >>= 1) {
                float ov = __shfl_xor_sync(0xffffffff, wv, o);
                int   oi = __shfl_xor_sync(0xffffffff, wi, o);
                if (ov > wv || (ov == wv && oi < wi)) { wv = ov; wi = oi; }
            }
            if (lane < 8 && wi == hi) p++;
            if (lane == 0) { rv_[r] = wv; sid[r] = wi; }
        }
        __syncwarp();
        if (lane < TOPK) {
            float e = expf(rv_[lane] - rv_[0]);
            float sum = e;
            #pragma unroll
            for (int o = 1; o < TOPK; o <<= 1)
                sum += __shfl_xor_sync(0xffff, sum, o);
            swgt[lane] = e / sum;
        }
    }
    __syncthreads();

    float wgt[TOPK]; int idn[TOPK];
    #pragma unroll
    for (int k = 0; k < TOPK; k++) { wgt[k] = swgt[k]; idn[k] = sid[k]; }
    const float4* a4 = (const float4*)g_adjsum;
    float4 acc = {0.f, 0.f, 0.f, 0.f};
    #pragma unroll
    for (int k = 0; k < TOPK; k++) {
        float4 vv = a4[(long long)idn[k] * (NN / 4) + tid];
        float wk = wgt[k];
        acc.x += wk * vv.x; acc.y += wk * vv.y; acc.z += wk * vv.z; acc.w += wk * vv.w;
    }
    ((float4*)g_nei)[(long long)row * (NN / 4) + tid] = acc;
}

// ---------------------------------------------------------------------------
// K4: partial[z][m,d] = sum_{n in z-chunk} nei[m,n]*kp[n,d]*rnorm[n]
// 64x64 tile, BK=32, 4x4 thread tile, f32x2 reg dup-pack, double buffer.
// ---------------------------------------------------------------------------
__global__ __launch_bounds__(256, 3)
void k_out_part(const float* __restrict__ kp) {
    __shared__ float As[2][32][68];
    __shared__ float Bs[2][32][68];
    int d0 = blockIdx.x * 64, m0 = blockIdx.y * 64;
    int kz = blockIdx.z;
    int t = threadIdx.x;
    int tx = t & 15, ty = t >> 4;        // tx: d-quad, ty: m-quad
    int am = t >> 2, aq = t & 3;         // A loader: row am, k-quads {aq, aq+4}
    int bk = t >> 4, bq = t & 15;        // B loader: k-rows {bk, bk+16}, d-quad bq
    const int KCH = NN / KSPLIT, NIT = KCH / 32;
    int kb = kz * KCH;

    float4 aP[2], bP[2]; float brnP[2];
    #pragma unroll
    for (int h = 0; h < 2; h++) {
        int q = aq + 4 * h, kr = bk + 16 * h;
        aP[h]   = *(const float4*)&g_nei[(long long)(m0 + am) * NN + kb + q * 4];
        brnP[h] = g_rnorm[kb + kr];
        bP[h]   = *(const float4*)&kp[(long long)(kb + kr) * D + d0 + bq * 4];
    }
    #pragma unroll
    for (int h = 0; h < 2; h++) {
        int q = aq + 4 * h, kr = bk + 16 * h;
        As[0][q * 4 + 0][am] = aP[h].x;
        As[0][q * 4 + 1][am] = aP[h].y;
        As[0][q * 4 + 2][am] = aP[h].z;
        As[0][q * 4 + 3][am] = aP[h].w;
        float4 bv = bP[h]; float s = brnP[h];
        bv.x *= s; bv.y *= s; bv.z *= s; bv.w *= s;
        *(float4*)&Bs[0][kr][bq * 4] = bv;
    }
    __syncthreads();

    unsigned long long acc[4][2] = {};
    int p = 0;
    for (int it = 0; it < NIT; it++) {
        if (it + 1 < NIT) {
            int k0 = kb + (it + 1) * 32;
            #pragma unroll
            for (int h = 0; h < 2; h++) {
                int q = aq + 4 * h, kr = bk + 16 * h;
                aP[h]   = *(const float4*)&g_nei[(long long)(m0 + am) * NN + k0 + q * 4];
                brnP[h] = g_rnorm[k0 + kr];
                bP[h]   = *(const float4*)&kp[(long long)(k0 + kr) * D + d0 + bq * 4];
            }
        }
        #pragma unroll
        for (int kk = 0; kk < 32; kk++) {
            float4 af = *(const float4*)&As[p][kk][ty * 4];
            ulonglong2 bb = *(const ulonglong2*)&Bs[p][kk][tx * 4];
            unsigned long long a0, a1, a2, a3;
            PACK_DUP(a0, af.x); PACK_DUP(a1, af.y);
            PACK_DUP(a2, af.z); PACK_DUP(a3, af.w);
            FMA_F32X2(acc[0][0], a0, bb.x, acc[0][0]);
            FMA_F32X2(acc[0][1], a0, bb.y, acc[0][1]);
            FMA_F32X2(acc[1][0], a1, bb.x, acc[1][0]);
            FMA_F32X2(acc[1][1], a1, bb.y, acc[1][1]);
            FMA_F32X2(acc[2][0], a2, bb.x, acc[2][0]);
            FMA_F32X2(acc[2][1], a2, bb.y, acc[2][1]);
            FMA_F32X2(acc[3][0], a3, bb.x, acc[3][0]);
            FMA_F32X2(acc[3][1], a3, bb.y, acc[3][1]);
        }
        if (it + 1 < NIT) {
            int pn = p ^ 1;
            #pragma unroll
            for (int h = 0; h < 2; h++) {
                int q = aq + 4 * h, kr = bk + 16 * h;
                As[pn][q * 4 + 0][am] = aP[h].x;
                As[pn][q * 4 + 1][am] = aP[h].y;
                As[pn][q * 4 + 2][am] = aP[h].z;
                As[pn][q * 4 + 3][am] = aP[h].w;
                float4 bv = bP[h]; float s = brnP[h];
                bv.x *= s; bv.y *= s; bv.z *= s; bv.w *= s;
                *(float4*)&Bs[pn][kr][bq * 4] = bv;
            }
        }
        __syncthreads();
        p ^= 1;
    }
    #pragma unroll
    for (int mm = 0; mm < 4; mm++) {
        float2 lo = *(float2*)&acc[mm][0];
        float2 hi = *(float2*)&acc[mm][1];
        float4 o = {lo.x, lo.y, hi.x, hi.y};
        *(float4*)&g_part[kz][(long long)(m0 + ty * 4 + mm) * D + d0 + tx * 4] = o;
    }
}

// K5: out = sum_z partial[z]
__global__ void k_reduce(float* __restrict__ out) {
    int i = blockIdx.x * blockDim.x + threadIdx.x;     // 49152 float4
    float4 acc = {0.f, 0.f, 0.f, 0.f};
    #pragma unroll
    for (int z = 0; z < KSPLIT; z++) {
        float4 v = ((const float4*)g_part[z])[i];
        acc.x += v.x; acc.y += v.y; acc.z += v.z; acc.w += v.w;
    }
    ((float4*)out)[i] = acc;
}

// ---------------------------------------------------------------------------
extern "C" void kernel_launch(void* const* d_in, const int* in_sizes, int n_in,
                              void* d_out, int out_size) {
    const float* pos = (const float*)d_in[0];   // (4,64,768) f32
    const float* kp  = (const float*)d_in[1];   // (2048,768) f32
    const float* adj = (const float*)d_in[2];   // (12,2048,2048) f32
    float* out = (float*)d_out;                 // (4,64,768) f32

    k_adjsum_rnorm<<<ADJ_BLOCKS + 16, 256>>>(adj, kp);
    k_scores<<<dim3(NN / 64, BP / 64, DSPLIT), 256>>>(pos, kp);
    k_topknei<<<BP, 512>>>();
    k_out_part<<<dim3(D / 64, BP / 64, KSPLIT), 256>>>(kp);
    k_reduce<<<BP * D / 4 / 256, 256>>>(out);
}